// round 14
// baseline (speedup 1.0000x reference)
#include <cuda_runtime.h>
#include <cuda_bf16.h>
#include <stdint.h>

#define NB   512      // batch (docs)
#define NS   512      // seq len
#define NV   50265    // vocab
#define PAD  1

#define SUM_BLOCKS   128
#define SUM_THREADS  256

#define NV_PAD       50268                    // round up to /4 for float4 zeroing
#define SMEM_BYTES   (NV_PAD * 4)             // 201,072 B dynamic smem (row buffer)

// Scratch (device globals only — no allocations allowed)
__device__ int g_part[SUM_BLOCKS];   // per-block partial non-pad counts (overwritten each replay)

// ---------------------------------------------------------------------------
// Kernel 1: grid-wide non-pad token count -> 128 partials (no reset needed).
// 128 blocks x 256 threads, each thread 2x int4 (8 ints). 1 MB total read.
// ---------------------------------------------------------------------------
__global__ void __launch_bounds__(SUM_THREADS) k_sum(const int* __restrict__ ids) {
    int t   = threadIdx.x;
    int gid = blockIdx.x * SUM_THREADS + t;
    const int4* p4 = (const int4*)ids;        // 65,536 int4 total
    int4 a = p4[gid * 2];
    int4 b = p4[gid * 2 + 1];
    int cnt = (a.x != PAD) + (a.y != PAD) + (a.z != PAD) + (a.w != PAD)
            + (b.x != PAD) + (b.y != PAD) + (b.z != PAD) + (b.w != PAD);

    #pragma unroll
    for (int o = 16; o; o >>= 1)
        cnt += __shfl_down_sync(0xffffffffu, cnt, o);

    __shared__ int red[8];
    if ((t & 31) == 0) red[t >> 5] = cnt;
    __syncthreads();
    if (t == 0) {
        int s = 0;
        #pragma unroll
        for (int i = 0; i < 8; i++) s += red[i];
        g_part[blockIdx.x] = s;
    }
}

// ---------------------------------------------------------------------------
// Kernel 2: one block per row, 512 threads, 201 KB dynamic smem = the row.
//   1. zero smem row (float4 STS)
//   2. smem atomicAdd(+1.0f) for the row's non-PAD tokens
//   3. own doc length (block reduce) + avgdl from g_part -> s_add
//   4. single smem->gmem streaming pass with inline BM25 transform:
//      all-zero float4 groups take the fast path (plain z4 store).
// Output is touched exactly once. No global atomics, no readback.
// ---------------------------------------------------------------------------
extern __shared__ float srow[];   // NV_PAD floats

__global__ void __launch_bounds__(512) k_big(const int* __restrict__ ids,
                                             float* __restrict__ out) {
    __shared__ int   red[16];
    __shared__ float s_add;

    int b = blockIdx.x;
    int t = threadIdx.x;

    int my = ids[b * NS + t];                 // own token (coalesced)

    // 1. zero the smem row
    float4* s4 = (float4*)srow;
    #pragma unroll 4
    for (int i = t; i < NV_PAD / 4; i += 512)
        s4[i] = make_float4(0.f, 0.f, 0.f, 0.f);
    __syncthreads();

    // 2. smem histogram (spread ATOMS)
    if (my != PAD)
        atomicAdd(&srow[my], 1.0f);

    // 3a. own doc length
    int cnt = (my != PAD);
    #pragma unroll
    for (int o = 16; o; o >>= 1)
        cnt += __shfl_down_sync(0xffffffffu, cnt, o);
    if ((t & 31) == 0) red[t >> 5] = cnt;

    // 3b. avgdl from the 128 partials (L2 hits)
    int pv = (t < SUM_BLOCKS) ? g_part[t] : 0;
    #pragma unroll
    for (int o = 16; o; o >>= 1)
        pv += __shfl_down_sync(0xffffffffu, pv, o);
    __shared__ int pred_[4];
    if (t < SUM_BLOCKS && (t & 31) == 0) pred_[t >> 5] = pv;
    __syncthreads();

    if (t == 0) {
        int dl = 0;
        #pragma unroll
        for (int i = 0; i < 16; i++) dl += red[i];
        int tot = pred_[0] + pred_[1] + pred_[2] + pred_[3];
        float avgdl = (float)tot / (float)NB;
        float d_avg = (float)dl / avgdl;
        s_add = 1.6f * (1.0f - 0.75f + 0.75f * d_avg);   // k*(1-b+b*d_avg)
    }
    __syncthreads();   // histogram complete + s_add published

    // 4. stream smem -> gmem once, transform inline.
    float add = s_add;
    float* row = out + (size_t)b * NV;
    // (b*NV) % 4 == b % 4  (NV % 4 == 1): rotating 16B alignment.
    int head = (4 - (b & 3)) & 3;
    if (t < head) {
        float c = srow[t];
        row[t] = (c == 0.0f) ? 0.0f : c * 2.6f / (c + add);
    }
    float4* r4 = (float4*)(row + head);
    int nvec   = (NV - head) >> 2;
    for (int i = t; i < nvec; i += 512) {
        int s = head + (i << 2);              // smem base (not 16B aligned; scalar LDS)
        float c0 = srow[s], c1 = srow[s + 1], c2 = srow[s + 2], c3 = srow[s + 3];
        float4 v;
        if (c0 == 0.0f && c1 == 0.0f && c2 == 0.0f && c3 == 0.0f) {
            v = make_float4(0.f, 0.f, 0.f, 0.f);          // fast path (~96%)
        } else {
            v.x = c0 * 2.6f / (c0 + add);                 // c==0 -> exact 0
            v.y = c1 * 2.6f / (c1 + add);
            v.z = c2 * 2.6f / (c2 + add);
            v.w = c3 * 2.6f / (c3 + add);
        }
        r4[i] = v;
    }
    int tail = head + (nvec << 2);            // <= 3 remaining scalars
    if (t < NV - tail) {
        float c = srow[tail + t];
        row[tail + t] = (c == 0.0f) ? 0.0f : c * 2.6f / (c + add);
    }
}

// ---------------------------------------------------------------------------
extern "C" void kernel_launch(void* const* d_in, const int* in_sizes, int n_in,
                              void* d_out, int out_size) {
    const int* ids = (const int*)d_in[0];
    float*     out = (float*)d_out;

    cudaFuncSetAttribute(k_big, cudaFuncAttributeMaxDynamicSharedMemorySize, SMEM_BYTES);

    k_sum<<<SUM_BLOCKS, SUM_THREADS>>>(ids);
    k_big<<<NB, 512, SMEM_BYTES>>>(ids, out);
}

// round 15
// speedup vs baseline: 1.3248x; 1.3248x over previous
#include <cuda_runtime.h>
#include <cuda_bf16.h>
#include <stdint.h>

#define NB   512      // batch (docs)
#define NS   512      // seq len
#define NV   50265    // vocab
#define PAD  1

#define SUM_BLOCKS   128
#define SUM_THREADS  256

#define BIG_THREADS  1024
#define NV_PAD       50272                    // NV + off(<=3) rounded up to /4
#define SMEM_BYTES   (NV_PAD * 4)             // 201,088 B dynamic smem (row buffer)

// Scratch (device globals only — no allocations allowed)
__device__ int g_part[SUM_BLOCKS];   // per-block partial non-pad counts (overwritten each replay)

// ---------------------------------------------------------------------------
// Kernel 1: grid-wide non-pad token count -> 128 partials (no reset needed).
// 128 blocks x 256 threads, each thread 2x int4 (8 ints). 1 MB total read.
// ---------------------------------------------------------------------------
__global__ void __launch_bounds__(SUM_THREADS) k_sum(const int* __restrict__ ids) {
    int t   = threadIdx.x;
    int gid = blockIdx.x * SUM_THREADS + t;
    const int4* p4 = (const int4*)ids;        // 65,536 int4 total
    int4 a = p4[gid * 2];
    int4 b = p4[gid * 2 + 1];
    int cnt = (a.x != PAD) + (a.y != PAD) + (a.z != PAD) + (a.w != PAD)
            + (b.x != PAD) + (b.y != PAD) + (b.z != PAD) + (b.w != PAD);

    #pragma unroll
    for (int o = 16; o; o >>= 1)
        cnt += __shfl_down_sync(0xffffffffu, cnt, o);

    __shared__ int red[8];
    if ((t & 31) == 0) red[t >> 5] = cnt;
    __syncthreads();
    if (t == 0) {
        int s = 0;
        #pragma unroll
        for (int i = 0; i < 8; i++) s += red[i];
        g_part[blockIdx.x] = s;
    }
}

// ---------------------------------------------------------------------------
// Kernel 2: one block per row, 1024 threads, 201 KB dynamic smem = the row.
// Histogram is stored SHIFTED by off = (4-head)&3 so that every gmem-aligned
// float4 group maps to an ALIGNED conflict-free LDS.128 (R14's 4-way-conflict
// scalar LDS was the disaster).
//   1. zero smem row (STS.128)
//   2. smem atomicAdd(+1.0f) at srow[off + token]   (threads 0..511)
//   3. own doclen + avgdl from g_part -> s_add
//   4. single smem->gmem stream: LDS.128 + (fast zero path | 4 divides) + STG.128
// Output touched exactly once; no global atomics; no second pass.
// ---------------------------------------------------------------------------
extern __shared__ float srow[];   // NV_PAD floats

__global__ void __launch_bounds__(BIG_THREADS) k_big(const int* __restrict__ ids,
                                                     float* __restrict__ out) {
    __shared__ int   red[16];
    __shared__ int   pred_[4];
    __shared__ float s_add;

    int b = blockIdx.x;
    int t = threadIdx.x;

    // Row alignment: (b*NV) % 4 == b % 4  (NV % 4 == 1).
    int head = (4 - (b & 3)) & 3;   // scalars before first aligned gmem group
    int off  = (4 - head) & 3;      // smem shift: off + head ≡ 0 (mod 4)

    int my = (t < NS) ? ids[b * NS + t] : PAD;   // own token (coalesced)

    // 1. zero the smem row (float4 STS, conflict-free)
    float4* s4 = (float4*)srow;
    const float4 z4 = make_float4(0.f, 0.f, 0.f, 0.f);
    #pragma unroll 4
    for (int i = t; i < NV_PAD / 4; i += BIG_THREADS)
        s4[i] = z4;
    __syncthreads();

    // 2. smem histogram (spread ATOMS), shifted by off
    if (t < NS && my != PAD)
        atomicAdd(&srow[off + my], 1.0f);

    // 3a. own doc length (warps 16..31 contribute 0)
    int cnt = (t < NS) ? (my != PAD) : 0;
    #pragma unroll
    for (int o = 16; o; o >>= 1)
        cnt += __shfl_down_sync(0xffffffffu, cnt, o);
    if ((t & 31) == 0 && (t >> 5) < 16) red[t >> 5] = cnt;

    // 3b. avgdl from the 128 partials (L2 hits)
    int pv = (t < SUM_BLOCKS) ? g_part[t] : 0;
    if (t < 128) {
        #pragma unroll
        for (int o = 16; o; o >>= 1)
            pv += __shfl_down_sync(0xffffffffu, pv, o);
        if ((t & 31) == 0) pred_[t >> 5] = pv;
    }
    __syncthreads();

    if (t == 0) {
        int dl = 0;
        #pragma unroll
        for (int i = 0; i < 16; i++) dl += red[i];
        int tot = pred_[0] + pred_[1] + pred_[2] + pred_[3];
        float avgdl = (float)tot / (float)NB;
        float d_avg = (float)dl / avgdl;
        s_add = 1.6f * (1.0f - 0.75f + 0.75f * d_avg);   // k*(1-b+b*d_avg)
    }
    __syncthreads();   // histogram complete + s_add published

    // 4. stream smem -> gmem once, transform inline.
    float add = s_add;
    float* row = out + (size_t)b * NV;

    if (t < head) {                              // 0..3 scalars before alignment
        float c = srow[off + t];
        row[t] = (c == 0.0f) ? 0.0f : c * 2.6f / (c + add);
    }

    float4* r4   = (float4*)(row + head);
    int     nvec = (NV - head) >> 2;             // aligned float4 groups
    int     sbase = (off + head) >> 2;           // aligned smem float4 index base
    for (int i = t; i < nvec; i += BIG_THREADS) {
        float4 c = s4[sbase + i];                // LDS.128, conflict-free
        float4 v;
        if (c.x == 0.0f && c.y == 0.0f && c.z == 0.0f && c.w == 0.0f) {
            v = z4;                              // fast path (~98%)
        } else {
            v.x = c.x * 2.6f / (c.x + add);      // c==0 -> exact 0
            v.y = c.y * 2.6f / (c.y + add);
            v.z = c.z * 2.6f / (c.z + add);
            v.w = c.w * 2.6f / (c.w + add);
        }
        r4[i] = v;
    }

    int tail = head + (nvec << 2);               // <= 3 remaining scalars
    if (t < NV - tail) {
        float c = srow[off + tail + t];
        row[tail + t] = (c == 0.0f) ? 0.0f : c * 2.6f / (c + add);
    }
}

// ---------------------------------------------------------------------------
extern "C" void kernel_launch(void* const* d_in, const int* in_sizes, int n_in,
                              void* d_out, int out_size) {
    const int* ids = (const int*)d_in[0];
    float*     out = (float*)d_out;

    cudaFuncSetAttribute(k_big, cudaFuncAttributeMaxDynamicSharedMemorySize, SMEM_BYTES);

    k_sum<<<SUM_BLOCKS, SUM_THREADS>>>(ids);
    k_big<<<NB, BIG_THREADS, SMEM_BYTES>>>(ids, out);
}

// round 17
// speedup vs baseline: 2.2469x; 1.6961x over previous
#include <cuda_runtime.h>
#include <cuda_bf16.h>
#include <stdint.h>

#define NB   512      // batch (docs)
#define NS   512      // seq len
#define NV   50265    // vocab
#define PAD  1
#define TOT  (NB * NV)          // 25,735,680 floats (div by 4)
#define NV4  (TOT / 4)          // 6,433,920 float4

#define GRID     592            // 148 SMs x 4 -> fully resident in one wave
#define THREADS  256
#define STRIDE   (GRID * THREADS)   // 151,552

// Scratch (device globals only — no allocations allowed)
__device__ int g_dl[NB];                       // doc lengths (overwritten each replay)
__device__ unsigned int g_arrive = 0;          // barrier counter (self-resetting)
__device__ volatile unsigned int g_sense = 0;  // barrier sense (flips each replay)

// ---------------------------------------------------------------------------
// Single fused kernel:
//  A) blocks 0..511: preload row tokens -> smem, doclen (hidden under fill)
//  B) all blocks: balanced linear float4 zero-fill slice      (~15.5us floor)
//  C) fence + grid barrier (sense-reversing, all-resident)    -> zeros visible
//  D) blocks 0..511: avgdl, spread global atomics (+1.0f exact),
//     leader (old==0) __ldcg readback + BM25 transform        (~1-2us, overlapped)
// ---------------------------------------------------------------------------
__global__ void __launch_bounds__(THREADS) k_all(const int* __restrict__ ids,
                                                 float* __restrict__ out) {
    __shared__ __align__(16) int toks[NS];
    __shared__ int   red[8];
    __shared__ int   s_dl;
    __shared__ float s_add;
    __shared__ unsigned int s_sense0;

    int b = blockIdx.x;
    int t = threadIdx.x;
    bool isrow = (b < NB);

    // ---- A: preload tokens + per-warp doclen partials (threads 0..127) ----
    if (isrow && t < 128) {
        int4 q = ((const int4*)(ids + b * NS))[t];
        ((int4*)toks)[t] = q;
        int cnt = (q.x != PAD) + (q.y != PAD) + (q.z != PAD) + (q.w != PAD);
        #pragma unroll
        for (int o = 16; o; o >>= 1)
            cnt += __shfl_down_sync(0xffffffffu, cnt, o);
        if ((t & 31) == 0) red[t >> 5] = cnt;
    }

    // ---- B: balanced zero-fill slice (pure store stream) ----
    float4* out4 = (float4*)out;
    const float4 z4 = make_float4(0.f, 0.f, 0.f, 0.f);
    for (int i = b * THREADS + t; i < NV4; i += STRIDE)
        out4[i] = z4;

    // ---- C: release stores, grid barrier ----
    __threadfence();
    __syncthreads();                       // red[] published; all fill stores fenced
    if (t == 0) {
        if (isrow) {
            int dl = red[0] + red[1] + red[2] + red[3];
            s_dl = dl;
            g_dl[b] = dl;
            __threadfence();               // publish g_dl[b] before arriving
        }
        unsigned int s0 = g_sense;         // read sense BEFORE arriving
        s_sense0 = s0;
        unsigned int a = atomicAdd(&g_arrive, 1u);
        if (a == GRID - 1) {               // last arrival: reset + flip
            g_arrive = 0;
            __threadfence();
            g_sense = s0 ^ 1u;
        }
    }
    if (!isrow) return;                    // fill-only blocks are done

    if (t == 0) {
        unsigned int s0 = s_sense0;
        while (g_sense == s0) { }          // wait for all fills + doclens
    }
    __syncthreads();

    // ---- D1: avgdl from g_dl (L2 hits, 2 loads/thread) ----
    int v = g_dl[t] + g_dl[t + 256];
    #pragma unroll
    for (int o = 16; o; o >>= 1)
        v += __shfl_down_sync(0xffffffffu, v, o);
    if ((t & 31) == 0) red[t >> 5] = v;
    __syncthreads();
    if (t == 0) {
        int tot = 0;
        #pragma unroll
        for (int i = 0; i < 8; i++) tot += red[i];
        float avgdl = (float)tot / (float)NB;
        float d_avg = (float)s_dl / avgdl;
        s_add = 1.6f * (1.0f - 0.75f + 0.75f * d_avg);   // k*(1-b+b*d_avg)
    }
    __syncthreads();

    // ---- D2: histogram via spread global atomics; leader election ----
    float* row = out + (size_t)b * NV;
    int my0 = toks[t];
    int my1 = toks[t + 256];
    bool l0 = false, l1 = false;
    if (my0 != PAD) l0 = (atomicAdd(&row[my0], 1.0f) == 0.0f);
    if (my1 != PAD) l1 = (atomicAdd(&row[my1], 1.0f) == 0.0f);
    __syncthreads();   // every thread held its atomics' returns => all performed

    // ---- D3: BM25 transform, single writer per (row, token) ----
    float add = s_add;
    if (l0) {
        float c = __ldcg(row + my0);       // L2 read (bypass stale L1 line)
        row[my0] = c * 2.6f / (c + add);   // (k+1) = 2.6
    }
    if (l1) {
        float c = __ldcg(row + my1);
        row[my1] = c * 2.6f / (c + add);
    }
}

// ---------------------------------------------------------------------------
extern "C" void kernel_launch(void* const* d_in, const int* in_sizes, int n_in,
                              void* d_out, int out_size) {
    const int* ids = (const int*)d_in[0];
    float*     out = (float*)d_out;
    k_all<<<GRID, THREADS>>>(ids, out);
}